// round 15
// baseline (speedup 1.0000x reference)
#include <cuda_runtime.h>

// ---------------------------------------------------------------------------
// AdaMix: self-paced patch mixing — SINGLE fused kernel (R15).
//   = R12 (the validated optimum) with the producer phase restructured into
//   512 UNIFORM blocks: each does one dice segment + the matching oconf and
//   aconf band. Producers now fit in <1 wave (512 < 592 slots), arrivals
//   drop 24->8 per sample (earlier map publication), grid 2560->1536.
//   blocks [0,512):    dice seg + conf bands; 8th arrival computes g_map[b]
//   blocks [512,1536): gather/scatter; spin on g_ready[b], copy 16 rows.
// ---------------------------------------------------------------------------

#define Bn    64
#define Cn    3
#define IMGn  256
#define NCn   4
#define Hn    32
#define Pn    64
#define TOPKn 16
#define NPIX  (IMGn * IMGn)   // 65536
#define NP4   (NPIX >> 2)     // 16384 float4 per plane
#define NSEG  8               // dice segments (= conf bands) per sample
#define ARRIVALS NSEG         // producer blocks per sample
#define NB_S1 (Bn * NSEG)          // 512 producer blocks
#define NB_SC (Bn * 16)            // 1024 scatter blocks (16 rows each)

// scratch (allocation-free: __device__ globals; zero-init, self-resetting)
__device__ double g_part[Bn][NSEG][8];   // [0:4)=inter, [4:8)=union
__device__ float  g_omean[Bn][Pn];
__device__ float  g_amean[Bn][Pn];
__device__ int    g_map[Bn][Pn];   // bit8 = use-augmented, low 8 = src patch
__device__ unsigned int g_done[Bn];      // producer arrivals
__device__ unsigned int g_ready[Bn];     // map published flag
__device__ unsigned int g_sdone[Bn];     // scatter arrivals (for reset)

// per-sample map: run by all 256 threads of the winning block
__device__ __forceinline__ void do_map(int b, int t) {
    __shared__ double s8[8];
    __shared__ float  s_ko[Pn], s_ka[Pn];
    __shared__ int    s_oidx[Pn], s_aidx[Pn];
    __shared__ int    s_k;
    __shared__ float  s_sign;

    if (t < 8) {
        double v = 0.0;
        #pragma unroll
        for (int s = 0; s < NSEG; s++) v += g_part[b][s][t];
        s8[t] = v;
    }
    __syncthreads();
    if (t == 0) {
        double dice = 0.0;
        #pragma unroll
        for (int c = 0; c < NCn; c++)
            dice += 2.0 * s8[c] / (s8[4 + c] + 1e-5);
        float lossf = (float)(1.0 - dice * 0.25);
        bool  mask  = lossf < 1.0f;                       // AGE = 1.0
        float spw   = 1.0f - lossf / (1.0f + 1e-5f);
        s_k    = min(TOPKn, (int)fabsf(truncf((float)TOPKn * spw)));
        s_sign = mask ? -1.0f : 1.0f;
    }
    __syncthreads();
    if (t < Pn) {
        s_ko[t] =  s_sign * g_omean[b][t];
        s_ka[t] = -s_sign * g_amean[b][t];
    }
    __syncthreads();
    if (t < Pn) {
        float mo = s_ko[t], ma = s_ka[t];
        int ro = 0, ra = 0;
        #pragma unroll
        for (int q = 0; q < Pn; q++) {
            float vo = s_ko[q]; ro += (vo < mo) || (vo == mo && q < t);
            float va = s_ka[q]; ra += (va < ma) || (va == ma && q < t);
        }
        s_oidx[ro] = t;
        s_aidx[ra] = t;
    }
    __syncthreads();
    if (t < Pn) {
        int dest = s_oidx[t];
        g_map[b][dest] = (t < s_k) ? (s_aidx[t] | 256) : dest;
    }
    __syncthreads();
    if (t == 0) {
        g_done[b] = 0;               // reset for next graph replay
        __threadfence();             // publish map before raising flag
        atomicExch(&g_ready[b], 1u);
    }
}

__global__ void __launch_bounds__(256, 4)
k_fused(const float* __restrict__ pred,
        const int*   __restrict__ olabel,
        const float* __restrict__ oimg,
        const float* __restrict__ aimg,
        const int*   __restrict__ olab,
        const int*   __restrict__ alab,
        const float* __restrict__ oconf,
        const float* __restrict__ aconf,
        float* __restrict__ out) {
    const int blk = blockIdx.x;
    const int t   = threadIdx.x;

    if (blk < NB_S1) {
        // ===== producer: dice segment + matching conf bands for sample b ====
        const int b   = blk >> 3;
        const int seg = blk & (NSEG - 1);
        const float4* p4 = (const float4*)(pred + (size_t)b * NCn * NPIX);
        const int4*   l4 = (const int4*)(olabel + (size_t)b * NPIX);
        const int base4 = seg * 2048;

        float inter[NCn] = {0, 0, 0, 0};
        float uni[NCn]   = {0, 0, 0, 0};

        // ---- dice main loop: MLP-10 batches (R12-proven) ----
        #pragma unroll
        for (int it = 0; it < 4; it++) {
            const int i4a = base4 + it * 512 + t;
            const int i4b = i4a + 256;
            // pred: single-use -> streaming; labels: default (reused by scatter)
            float4 a0 = __ldcs(&p4[i4a]);
            float4 a1 = __ldcs(&p4[i4a + NP4]);
            float4 a2 = __ldcs(&p4[i4a + 2 * NP4]);
            float4 a3 = __ldcs(&p4[i4a + 3 * NP4]);
            int4   lA = l4[i4a];
            float4 b0 = __ldcs(&p4[i4b]);
            float4 b1 = __ldcs(&p4[i4b + NP4]);
            float4 b2 = __ldcs(&p4[i4b + 2 * NP4]);
            float4 b3 = __ldcs(&p4[i4b + 3 * NP4]);
            int4   lB = l4[i4b];

            #pragma unroll
            for (int g = 0; g < 2; g++) {
                float x0[4], x1[4], x2[4], x3[4];
                int   lv[4];
                if (g == 0) {
                    x0[0]=a0.x; x0[1]=a0.y; x0[2]=a0.z; x0[3]=a0.w;
                    x1[0]=a1.x; x1[1]=a1.y; x1[2]=a1.z; x1[3]=a1.w;
                    x2[0]=a2.x; x2[1]=a2.y; x2[2]=a2.z; x2[3]=a2.w;
                    x3[0]=a3.x; x3[1]=a3.y; x3[2]=a3.z; x3[3]=a3.w;
                    lv[0]=lA.x; lv[1]=lA.y; lv[2]=lA.z; lv[3]=lA.w;
                } else {
                    x0[0]=b0.x; x0[1]=b0.y; x0[2]=b0.z; x0[3]=b0.w;
                    x1[0]=b1.x; x1[1]=b1.y; x1[2]=b1.z; x1[3]=b1.w;
                    x2[0]=b2.x; x2[1]=b2.y; x2[2]=b2.z; x2[3]=b2.w;
                    x3[0]=b3.x; x3[1]=b3.y; x3[2]=b3.z; x3[3]=b3.w;
                    lv[0]=lB.x; lv[1]=lB.y; lv[2]=lB.z; lv[3]=lB.w;
                }
                #pragma unroll
                for (int j = 0; j < 4; j++) {
                    float e0 = __expf(x0[j]), e1 = __expf(x1[j]);
                    float e2 = __expf(x2[j]), e3 = __expf(x3[j]);
                    float inv = __frcp_rn((e0 + e1) + (e2 + e3));
                    float s[NCn] = {e0 * inv, e1 * inv, e2 * inv, e3 * inv};
                    const int lab = lv[j];
                    #pragma unroll
                    for (int c = 0; c < NCn; c++) {
                        float f = (lab == c) ? 1.0f : 0.0f;
                        inter[c] = fmaf(f, s[c], inter[c]);
                        uni[c]  += s[c] + f;
                    }
                }
            }
        }

        // ---- dice epilogue: float shared reduce, one warp per quantity ----
        __shared__ float sred[8][256];
        #pragma unroll
        for (int q = 0; q < NCn; q++) {
            sred[q][t]     = inter[q];
            sred[4 + q][t] = uni[q];
        }
        __syncthreads();
        {
            const int w = t >> 5, lane = t & 31;
            float v = sred[w][lane];
            #pragma unroll
            for (int j = 1; j < 8; j++) v += sred[w][lane + 32 * j];
            #pragma unroll
            for (int o = 16; o > 0; o >>= 1)
                v += __shfl_down_sync(0xffffffffu, v, o);
            if (lane == 0) g_part[b][seg][w] = (double)v;
        }

        // ---- conf means: band 'seg' of oconf and aconf (32KB each) ----
        {
            const float4* osrc = (const float4*)(oconf + (size_t)b * NPIX
                                                 + seg * Hn * IMGn);
            const float4* asrc = (const float4*)(aconf + (size_t)b * NPIX
                                                 + seg * Hn * IMGn);
            float acco = 0.0f, acca = 0.0f;
            #pragma unroll
            for (int it = 0; it < 8; it++) {
                float4 vo = osrc[it * 256 + t];
                float4 va = asrc[it * 256 + t];
                acco += (vo.x + vo.y) + (vo.z + vo.w);
                acca += (va.x + va.y) + (va.z + va.w);
            }
            __syncthreads();   // dice epilogue done with sred
            sred[0][t] = acco;
            sred[1][t] = acca;
            __syncthreads();
            if (t < 16) {
                const int src = t >> 3;      // 0 = o, 1 = a
                const int pc  = t & 7;       // patch column within band
                float tot = 0.0f;
                #pragma unroll
                for (int g = 0; g < 4; g++)
                    #pragma unroll
                    for (int j = 0; j < 8; j++)
                        tot += sred[src][g * 64 + pc * 8 + j];
                float mean = tot * (1.0f / (Hn * Hn));
                if (src) g_amean[b][seg * 8 + pc] = mean;
                else     g_omean[b][seg * 8 + pc] = mean;
            }
        }

        // ---- arrival: 8th producer block for sample b computes its map ----
        __syncthreads();
        __threadfence();
        __shared__ int s_win;
        if (t == 0)
            s_win = (atomicAdd(&g_done[b], 1u) == ARRIVALS - 1) ? 1 : 0;
        __syncthreads();
        if (s_win) { __threadfence(); do_map(b, t); }

    } else {
        // ===== scatter: wait for map, then copy 16 rows (R12 granularity) ===
        const int m    = blk - NB_S1;
        const int b    = m >> 4;
        const int band = m & 15;            // 16 dest rows: band*16..band*16+15

        if (t == 0) {
            while (atomicAdd(&g_ready[b], 0u) == 0u) __nanosleep(64);
        }
        __syncthreads();
        __threadfence();   // acquire: map visible

        const int r  = t >> 6;              // 0..3
        const int c4 = t & 63;
        const int x  = c4 << 2;
        const int y0 = (band << 4) + r;     // rows y0, +4, +8, +12 (same patch)
        const int p  = ((y0 >> 5) << 3) | (x >> 5);

        const int v    = *(volatile int*)&g_map[b][p];   // bypass L1
        const int q    = v & 255;
        const bool sel = (v & 256) != 0;
        const int sx   = ((q & 7) << 5) | (x & 31);
        const int qy   = (q >> 3) << 5;

        const size_t bpl4 = (size_t)b * NP4;
        const float4* img4 = (const float4*)(sel ? aimg : oimg);
        const int4*   lab4 = (const int4*)  (sel ? alab : olab);
        const float4* cnf4 = (const float4*)(sel ? aconf : oconf);
        float4* o4 = (float4*)out;

        const size_t ib4 = (size_t)b * Cn * NP4;
        const size_t LB4 = (size_t)Bn * Cn * NP4;
        const size_t CB4 = LB4 + (size_t)Bn * NP4;

        #pragma unroll
        for (int half = 0; half < 2; half++) {
            const int yA = y0 + half * 8;            // rows yA and yA+4
            const size_t d0 = (size_t)yA * 64 + c4;
            const size_t d1 = d0 + 4 * 64;
            const size_t s0 = ((size_t)(qy | (yA & 31)) * IMGn + sx) >> 2;
            const size_t s1 = s0 + 4 * 64;

            // batch: 10 loads in flight, then 10 streaming stores
            float4 i0a = __ldcs(&img4[ib4 + 0 * NP4 + s0]);
            float4 i1a = __ldcs(&img4[ib4 + 1 * NP4 + s0]);
            float4 i2a = __ldcs(&img4[ib4 + 2 * NP4 + s0]);
            float4 i0b = __ldcs(&img4[ib4 + 0 * NP4 + s1]);
            float4 i1b = __ldcs(&img4[ib4 + 1 * NP4 + s1]);
            float4 i2b = __ldcs(&img4[ib4 + 2 * NP4 + s1]);
            int4   lva = lab4[bpl4 + s0];
            int4   lvb = lab4[bpl4 + s1];
            float4 cva = cnf4[bpl4 + s0];
            float4 cvb = cnf4[bpl4 + s1];

            __stcs(&o4[ib4 + 0 * NP4 + d0], i0a);
            __stcs(&o4[ib4 + 1 * NP4 + d0], i1a);
            __stcs(&o4[ib4 + 2 * NP4 + d0], i2a);
            __stcs(&o4[ib4 + 0 * NP4 + d1], i0b);
            __stcs(&o4[ib4 + 1 * NP4 + d1], i1b);
            __stcs(&o4[ib4 + 2 * NP4 + d1], i2b);
            __stcs(&o4[LB4 + bpl4 + d0],
                   make_float4((float)lva.x, (float)lva.y,
                               (float)lva.z, (float)lva.w));
            __stcs(&o4[LB4 + bpl4 + d1],
                   make_float4((float)lvb.x, (float)lvb.y,
                               (float)lvb.z, (float)lvb.w));
            __stcs(&o4[CB4 + bpl4 + d0], cva);
            __stcs(&o4[CB4 + bpl4 + d1], cvb);
        }

        // reset protocol: last scatter block for b clears flags for replay
        __syncthreads();
        if (t == 0) {
            if (atomicAdd(&g_sdone[b], 1u) == 15u) {
                g_sdone[b] = 0;
                atomicExch(&g_ready[b], 0u);
            }
        }
    }
}

extern "C" void kernel_launch(void* const* d_in, const int* in_sizes, int n_in,
                              void* d_out, int out_size) {
    const float* oimage = (const float*)d_in[0];
    const float* aimage = (const float*)d_in[1];
    const int*   olabel = (const int*)  d_in[2];
    const int*   alabel = (const int*)  d_in[3];
    const float* oconf  = (const float*)d_in[4];
    const float* aconf  = (const float*)d_in[5];
    const float* pred   = (const float*)d_in[6];
    float* out = (float*)d_out;

    k_fused<<<NB_S1 + NB_SC, 256>>>(pred, olabel, oimage, aimage,
                                    olabel, alabel, oconf, aconf, out);
}

// round 16
// speedup vs baseline: 1.0143x; 1.0143x over previous
#include <cuda_runtime.h>

// ---------------------------------------------------------------------------
// AdaMix: self-paced patch mixing — SINGLE fused kernel (R16 = R12 final).
//   R12 configuration (validated optimum across all swept axes: MLP-10 dice,
//   64 regs / 4 CTA/SM, 1024 scatter blocks, L2 retention for labels/conf)
//   + last-use .cs on scatter's label/conf reads (free L2 ways in the tail).
//   blocks [0,512):     dice partials (8 seg/sample)
//   blocks [512,1536):  per-patch conf means
//     -> 24th arriving block per sample computes loss->k, rank-sort, g_map
//   blocks [1536,2560): gather/scatter; spin on g_ready[b], copy 16 rows.
// ---------------------------------------------------------------------------

#define Bn    64
#define Cn    3
#define IMGn  256
#define NCn   4
#define Hn    32
#define Pn    64
#define TOPKn 16
#define NPIX  (IMGn * IMGn)   // 65536
#define NP4   (NPIX >> 2)     // 16384 float4 per plane
#define NSEG  8               // dice segments per sample
#define ARRIVALS (NSEG + 16)  // stage1 blocks contributing to one sample
#define NB_S1 (Bn * NSEG + 1024)   // 1536
#define NB_SC (Bn * 16)            // 1024 scatter blocks (16 rows each)

// scratch (allocation-free: __device__ globals; zero-init, self-resetting)
__device__ double g_part[Bn][NSEG][8];   // [0:4)=inter, [4:8)=union
__device__ float  g_omean[Bn][Pn];
__device__ float  g_amean[Bn][Pn];
__device__ int    g_map[Bn][Pn];   // bit8 = use-augmented, low 8 = src patch
__device__ unsigned int g_done[Bn];      // stage1 arrivals
__device__ unsigned int g_ready[Bn];     // map published flag
__device__ unsigned int g_sdone[Bn];     // scatter arrivals (for reset)

// per-sample map: run by all 256 threads of the winning block
__device__ __forceinline__ void do_map(int b, int t) {
    __shared__ double s8[8];
    __shared__ float  s_ko[Pn], s_ka[Pn];
    __shared__ int    s_oidx[Pn], s_aidx[Pn];
    __shared__ int    s_k;
    __shared__ float  s_sign;

    if (t < 8) {
        double v = 0.0;
        #pragma unroll
        for (int s = 0; s < NSEG; s++) v += g_part[b][s][t];
        s8[t] = v;
    }
    __syncthreads();
    if (t == 0) {
        double dice = 0.0;
        #pragma unroll
        for (int c = 0; c < NCn; c++)
            dice += 2.0 * s8[c] / (s8[4 + c] + 1e-5);
        float lossf = (float)(1.0 - dice * 0.25);
        bool  mask  = lossf < 1.0f;                       // AGE = 1.0
        float spw   = 1.0f - lossf / (1.0f + 1e-5f);
        s_k    = min(TOPKn, (int)fabsf(truncf((float)TOPKn * spw)));
        s_sign = mask ? -1.0f : 1.0f;
    }
    __syncthreads();
    if (t < Pn) {
        s_ko[t] =  s_sign * g_omean[b][t];
        s_ka[t] = -s_sign * g_amean[b][t];
    }
    __syncthreads();
    if (t < Pn) {
        float mo = s_ko[t], ma = s_ka[t];
        int ro = 0, ra = 0;
        #pragma unroll
        for (int q = 0; q < Pn; q++) {
            float vo = s_ko[q]; ro += (vo < mo) || (vo == mo && q < t);
            float va = s_ka[q]; ra += (va < ma) || (va == ma && q < t);
        }
        s_oidx[ro] = t;
        s_aidx[ra] = t;
    }
    __syncthreads();
    if (t < Pn) {
        int dest = s_oidx[t];
        g_map[b][dest] = (t < s_k) ? (s_aidx[t] | 256) : dest;
    }
    __syncthreads();
    if (t == 0) {
        g_done[b] = 0;               // reset for next graph replay
        __threadfence();             // publish map before raising flag
        atomicExch(&g_ready[b], 1u);
    }
}

__global__ void __launch_bounds__(256, 4)
k_fused(const float* __restrict__ pred,
        const int*   __restrict__ olabel,
        const float* __restrict__ oimg,
        const float* __restrict__ aimg,
        const int*   __restrict__ olab,
        const int*   __restrict__ alab,
        const float* __restrict__ oconf,
        const float* __restrict__ aconf,
        float* __restrict__ out) {
    const int blk = blockIdx.x;
    const int t   = threadIdx.x;

    if (blk < Bn * NSEG) {
        // ================= dice partials: b = blk>>3, seg = blk&7 ==========
        const int b   = blk >> 3;
        const int seg = blk & (NSEG - 1);
        const float4* p4 = (const float4*)(pred + (size_t)b * NCn * NPIX);
        const int4*   l4 = (const int4*)(olabel + (size_t)b * NPIX);
        const int base4 = seg * 2048;

        float inter[NCn] = {0, 0, 0, 0};
        float uni[NCn]   = {0, 0, 0, 0};

        #pragma unroll
        for (int it = 0; it < 4; it++) {
            const int i4a = base4 + it * 512 + t;
            const int i4b = i4a + 256;
            // pred: single-use -> streaming; labels: default (reused by scatter)
            float4 a0 = __ldcs(&p4[i4a]);
            float4 a1 = __ldcs(&p4[i4a + NP4]);
            float4 a2 = __ldcs(&p4[i4a + 2 * NP4]);
            float4 a3 = __ldcs(&p4[i4a + 3 * NP4]);
            int4   lA = l4[i4a];
            float4 b0 = __ldcs(&p4[i4b]);
            float4 b1 = __ldcs(&p4[i4b + NP4]);
            float4 b2 = __ldcs(&p4[i4b + 2 * NP4]);
            float4 b3 = __ldcs(&p4[i4b + 3 * NP4]);
            int4   lB = l4[i4b];

            #pragma unroll
            for (int g = 0; g < 2; g++) {
                float x0[4], x1[4], x2[4], x3[4];
                int   lv[4];
                if (g == 0) {
                    x0[0]=a0.x; x0[1]=a0.y; x0[2]=a0.z; x0[3]=a0.w;
                    x1[0]=a1.x; x1[1]=a1.y; x1[2]=a1.z; x1[3]=a1.w;
                    x2[0]=a2.x; x2[1]=a2.y; x2[2]=a2.z; x2[3]=a2.w;
                    x3[0]=a3.x; x3[1]=a3.y; x3[2]=a3.z; x3[3]=a3.w;
                    lv[0]=lA.x; lv[1]=lA.y; lv[2]=lA.z; lv[3]=lA.w;
                } else {
                    x0[0]=b0.x; x0[1]=b0.y; x0[2]=b0.z; x0[3]=b0.w;
                    x1[0]=b1.x; x1[1]=b1.y; x1[2]=b1.z; x1[3]=b1.w;
                    x2[0]=b2.x; x2[1]=b2.y; x2[2]=b2.z; x2[3]=b2.w;
                    x3[0]=b3.x; x3[1]=b3.y; x3[2]=b3.z; x3[3]=b3.w;
                    lv[0]=lB.x; lv[1]=lB.y; lv[2]=lB.z; lv[3]=lB.w;
                }
                #pragma unroll
                for (int j = 0; j < 4; j++) {
                    float e0 = __expf(x0[j]), e1 = __expf(x1[j]);
                    float e2 = __expf(x2[j]), e3 = __expf(x3[j]);
                    float inv = __frcp_rn((e0 + e1) + (e2 + e3));
                    float s[NCn] = {e0 * inv, e1 * inv, e2 * inv, e3 * inv};
                    const int lab = lv[j];
                    #pragma unroll
                    for (int c = 0; c < NCn; c++) {
                        float f = (lab == c) ? 1.0f : 0.0f;
                        inter[c] = fmaf(f, s[c], inter[c]);
                        uni[c]  += s[c] + f;
                    }
                }
            }
        }

        __shared__ float sred[8][256];
        #pragma unroll
        for (int q = 0; q < NCn; q++) {
            sred[q][t]     = inter[q];
            sred[4 + q][t] = uni[q];
        }
        __syncthreads();
        const int w = t >> 5, lane = t & 31;
        float v = sred[w][lane];
        #pragma unroll
        for (int j = 1; j < 8; j++) v += sred[w][lane + 32 * j];
        #pragma unroll
        for (int o = 16; o > 0; o >>= 1) v += __shfl_down_sync(0xffffffffu, v, o);
        if (lane == 0) g_part[b][seg][w] = (double)v;

        // arrival
        __syncthreads();
        __threadfence();
        __shared__ int s_win;
        if (t == 0)
            s_win = (atomicAdd(&g_done[b], 1u) == ARRIVALS - 1) ? 1 : 0;
        __syncthreads();
        if (s_win) { __threadfence(); do_map(b, t); }

    } else if (blk < NB_S1) {
        // ================= patch means (conf: default policy, reused) =======
        const int m    = blk - Bn * NSEG;
        const int b    = m >> 4;
        const int s    = (m >> 3) & 1;
        const int band = m & 7;
        const float4* src = (const float4*)((s ? aconf : oconf)
                              + (size_t)b * NPIX + band * Hn * IMGn);
        float acc = 0.0f;
        #pragma unroll
        for (int it = 0; it < 8; it++) {
            float4 v = src[it * 256 + t];
            acc += (v.x + v.y) + (v.z + v.w);
        }
        __shared__ float sacc[256];
        sacc[t] = acc;
        __syncthreads();
        if (t < 8) {
            float tot = 0.0f;
            #pragma unroll
            for (int g = 0; g < 4; g++)
                #pragma unroll
                for (int j = 0; j < 8; j++)
                    tot += sacc[g * 64 + t * 8 + j];
            float mean = tot * (1.0f / (Hn * Hn));
            if (s) g_amean[b][band * 8 + t] = mean;
            else   g_omean[b][band * 8 + t] = mean;
        }

        // arrival
        __syncthreads();
        __threadfence();
        __shared__ int s_win;
        if (t == 0)
            s_win = (atomicAdd(&g_done[b], 1u) == ARRIVALS - 1) ? 1 : 0;
        __syncthreads();
        if (s_win) { __threadfence(); do_map(b, t); }

    } else {
        // ================= scatter: wait for map, then copy 16 rows =========
        const int m    = blk - NB_S1;
        const int b    = m >> 4;
        const int band = m & 15;            // 16 dest rows: band*16..band*16+15

        if (t == 0) {
            while (atomicAdd(&g_ready[b], 0u) == 0u) __nanosleep(64);
        }
        __syncthreads();
        __threadfence();   // acquire: map visible

        const int r  = t >> 6;              // 0..3
        const int c4 = t & 63;
        const int x  = c4 << 2;
        const int y0 = (band << 4) + r;     // rows y0, +4, +8, +12 (same patch)
        const int p  = ((y0 >> 5) << 3) | (x >> 5);

        const int v    = *(volatile int*)&g_map[b][p];   // bypass L1
        const int q    = v & 255;
        const bool sel = (v & 256) != 0;
        const int sx   = ((q & 7) << 5) | (x & 31);
        const int qy   = (q >> 3) << 5;

        const size_t bpl4 = (size_t)b * NP4;
        const float4* img4 = (const float4*)(sel ? aimg : oimg);
        const int4*   lab4 = (const int4*)  (sel ? alab : olab);
        const float4* cnf4 = (const float4*)(sel ? aconf : oconf);
        float4* o4 = (float4*)out;

        const size_t ib4 = (size_t)b * Cn * NP4;
        const size_t LB4 = (size_t)Bn * Cn * NP4;
        const size_t CB4 = LB4 + (size_t)Bn * NP4;

        #pragma unroll
        for (int half = 0; half < 2; half++) {
            const int yA = y0 + half * 8;            // rows yA and yA+4
            const size_t d0 = (size_t)yA * 64 + c4;
            const size_t d1 = d0 + 4 * 64;
            const size_t s0 = ((size_t)(qy | (yA & 31)) * IMGn + sx) >> 2;
            const size_t s1 = s0 + 4 * 64;

            // batch: 10 loads in flight, then 10 streaming stores.
            // labels/conf: LAST use of the L2-retained lines -> .cs evict-first
            float4 i0a = __ldcs(&img4[ib4 + 0 * NP4 + s0]);
            float4 i1a = __ldcs(&img4[ib4 + 1 * NP4 + s0]);
            float4 i2a = __ldcs(&img4[ib4 + 2 * NP4 + s0]);
            float4 i0b = __ldcs(&img4[ib4 + 0 * NP4 + s1]);
            float4 i1b = __ldcs(&img4[ib4 + 1 * NP4 + s1]);
            float4 i2b = __ldcs(&img4[ib4 + 2 * NP4 + s1]);
            int4   lva = __ldcs(&lab4[bpl4 + s0]);
            int4   lvb = __ldcs(&lab4[bpl4 + s1]);
            float4 cva = __ldcs(&cnf4[bpl4 + s0]);
            float4 cvb = __ldcs(&cnf4[bpl4 + s1]);

            __stcs(&o4[ib4 + 0 * NP4 + d0], i0a);
            __stcs(&o4[ib4 + 1 * NP4 + d0], i1a);
            __stcs(&o4[ib4 + 2 * NP4 + d0], i2a);
            __stcs(&o4[ib4 + 0 * NP4 + d1], i0b);
            __stcs(&o4[ib4 + 1 * NP4 + d1], i1b);
            __stcs(&o4[ib4 + 2 * NP4 + d1], i2b);
            __stcs(&o4[LB4 + bpl4 + d0],
                   make_float4((float)lva.x, (float)lva.y,
                               (float)lva.z, (float)lva.w));
            __stcs(&o4[LB4 + bpl4 + d1],
                   make_float4((float)lvb.x, (float)lvb.y,
                               (float)lvb.z, (float)lvb.w));
            __stcs(&o4[CB4 + bpl4 + d0], cva);
            __stcs(&o4[CB4 + bpl4 + d1], cvb);
        }

        // reset protocol: last scatter block for b clears flags for replay
        __syncthreads();
        if (t == 0) {
            if (atomicAdd(&g_sdone[b], 1u) == 15u) {
                g_sdone[b] = 0;
                atomicExch(&g_ready[b], 0u);
            }
        }
    }
}

extern "C" void kernel_launch(void* const* d_in, const int* in_sizes, int n_in,
                              void* d_out, int out_size) {
    const float* oimage = (const float*)d_in[0];
    const float* aimage = (const float*)d_in[1];
    const int*   olabel = (const int*)  d_in[2];
    const int*   alabel = (const int*)  d_in[3];
    const float* oconf  = (const float*)d_in[4];
    const float* aconf  = (const float*)d_in[5];
    const float* pred   = (const float*)d_in[6];
    float* out = (float*)d_out;

    k_fused<<<NB_S1 + NB_SC, 256>>>(pred, olabel, oimage, aimage,
                                    olabel, alabel, oconf, aconf, out);
}

// round 17
// speedup vs baseline: 1.0184x; 1.0041x over previous
#include <cuda_runtime.h>

// ---------------------------------------------------------------------------
// AdaMix: self-paced patch mixing — SINGLE fused kernel (R17).
//   R16 (validated optimum config) + per-sample CONTIGUOUS producer blocks:
//   blk = 24*b + sub (sub<8: dice seg, sub>=8: conf-mean band). Sample b's
//   map publishes as soon as its own 24 co-resident blocks finish, streaming
//   map availability in the same b-order the scatter blocks consume.
//   blocks [0,1536):    producers (dice + means, grouped per sample)
//     -> 24th arriving block per sample computes loss->k, rank-sort, g_map
//   blocks [1536,2560): gather/scatter; spin on g_ready[b], copy 16 rows.
// ---------------------------------------------------------------------------

#define Bn    64
#define Cn    3
#define IMGn  256
#define NCn   4
#define Hn    32
#define Pn    64
#define TOPKn 16
#define NPIX  (IMGn * IMGn)   // 65536
#define NP4   (NPIX >> 2)     // 16384 float4 per plane
#define NSEG  8               // dice segments per sample
#define ARRIVALS (NSEG + 16)  // producer blocks per sample (8 dice + 16 means)
#define NB_S1 (Bn * ARRIVALS)      // 1536
#define NB_SC (Bn * 16)            // 1024 scatter blocks (16 rows each)

// scratch (allocation-free: __device__ globals; zero-init, self-resetting)
__device__ double g_part[Bn][NSEG][8];   // [0:4)=inter, [4:8)=union
__device__ float  g_omean[Bn][Pn];
__device__ float  g_amean[Bn][Pn];
__device__ int    g_map[Bn][Pn];   // bit8 = use-augmented, low 8 = src patch
__device__ unsigned int g_done[Bn];      // producer arrivals
__device__ unsigned int g_ready[Bn];     // map published flag
__device__ unsigned int g_sdone[Bn];     // scatter arrivals (for reset)

// per-sample map: run by all 256 threads of the winning block
__device__ __forceinline__ void do_map(int b, int t) {
    __shared__ double s8[8];
    __shared__ float  s_ko[Pn], s_ka[Pn];
    __shared__ int    s_oidx[Pn], s_aidx[Pn];
    __shared__ int    s_k;
    __shared__ float  s_sign;

    if (t < 8) {
        double v = 0.0;
        #pragma unroll
        for (int s = 0; s < NSEG; s++) v += g_part[b][s][t];
        s8[t] = v;
    }
    __syncthreads();
    if (t == 0) {
        double dice = 0.0;
        #pragma unroll
        for (int c = 0; c < NCn; c++)
            dice += 2.0 * s8[c] / (s8[4 + c] + 1e-5);
        float lossf = (float)(1.0 - dice * 0.25);
        bool  mask  = lossf < 1.0f;                       // AGE = 1.0
        float spw   = 1.0f - lossf / (1.0f + 1e-5f);
        s_k    = min(TOPKn, (int)fabsf(truncf((float)TOPKn * spw)));
        s_sign = mask ? -1.0f : 1.0f;
    }
    __syncthreads();
    if (t < Pn) {
        s_ko[t] =  s_sign * g_omean[b][t];
        s_ka[t] = -s_sign * g_amean[b][t];
    }
    __syncthreads();
    if (t < Pn) {
        float mo = s_ko[t], ma = s_ka[t];
        int ro = 0, ra = 0;
        #pragma unroll
        for (int q = 0; q < Pn; q++) {
            float vo = s_ko[q]; ro += (vo < mo) || (vo == mo && q < t);
            float va = s_ka[q]; ra += (va < ma) || (va == ma && q < t);
        }
        s_oidx[ro] = t;
        s_aidx[ra] = t;
    }
    __syncthreads();
    if (t < Pn) {
        int dest = s_oidx[t];
        g_map[b][dest] = (t < s_k) ? (s_aidx[t] | 256) : dest;
    }
    __syncthreads();
    if (t == 0) {
        g_done[b] = 0;               // reset for next graph replay
        __threadfence();             // publish map before raising flag
        atomicExch(&g_ready[b], 1u);
    }
}

__global__ void __launch_bounds__(256, 4)
k_fused(const float* __restrict__ pred,
        const int*   __restrict__ olabel,
        const float* __restrict__ oimg,
        const float* __restrict__ aimg,
        const int*   __restrict__ olab,
        const int*   __restrict__ alab,
        const float* __restrict__ oconf,
        const float* __restrict__ aconf,
        float* __restrict__ out) {
    const int blk = blockIdx.x;
    const int t   = threadIdx.x;

    if (blk < NB_S1) {
        // ===== producers, grouped per sample: b = blk/24, sub = blk%24 ======
        const int b   = blk / ARRIVALS;
        const int sub = blk - b * ARRIVALS;

        if (sub < NSEG) {
            // ---------------- dice partials: segment = sub ------------------
            const int seg = sub;
            const float4* p4 = (const float4*)(pred + (size_t)b * NCn * NPIX);
            const int4*   l4 = (const int4*)(olabel + (size_t)b * NPIX);
            const int base4 = seg * 2048;

            float inter[NCn] = {0, 0, 0, 0};
            float uni[NCn]   = {0, 0, 0, 0};

            #pragma unroll
            for (int it = 0; it < 4; it++) {
                const int i4a = base4 + it * 512 + t;
                const int i4b = i4a + 256;
                // pred: single-use -> streaming; labels: default (reused later)
                float4 a0 = __ldcs(&p4[i4a]);
                float4 a1 = __ldcs(&p4[i4a + NP4]);
                float4 a2 = __ldcs(&p4[i4a + 2 * NP4]);
                float4 a3 = __ldcs(&p4[i4a + 3 * NP4]);
                int4   lA = l4[i4a];
                float4 b0 = __ldcs(&p4[i4b]);
                float4 b1 = __ldcs(&p4[i4b + NP4]);
                float4 b2 = __ldcs(&p4[i4b + 2 * NP4]);
                float4 b3 = __ldcs(&p4[i4b + 3 * NP4]);
                int4   lB = l4[i4b];

                #pragma unroll
                for (int g = 0; g < 2; g++) {
                    float x0[4], x1[4], x2[4], x3[4];
                    int   lv[4];
                    if (g == 0) {
                        x0[0]=a0.x; x0[1]=a0.y; x0[2]=a0.z; x0[3]=a0.w;
                        x1[0]=a1.x; x1[1]=a1.y; x1[2]=a1.z; x1[3]=a1.w;
                        x2[0]=a2.x; x2[1]=a2.y; x2[2]=a2.z; x2[3]=a2.w;
                        x3[0]=a3.x; x3[1]=a3.y; x3[2]=a3.z; x3[3]=a3.w;
                        lv[0]=lA.x; lv[1]=lA.y; lv[2]=lA.z; lv[3]=lA.w;
                    } else {
                        x0[0]=b0.x; x0[1]=b0.y; x0[2]=b0.z; x0[3]=b0.w;
                        x1[0]=b1.x; x1[1]=b1.y; x1[2]=b1.z; x1[3]=b1.w;
                        x2[0]=b2.x; x2[1]=b2.y; x2[2]=b2.z; x2[3]=b2.w;
                        x3[0]=b3.x; x3[1]=b3.y; x3[2]=b3.z; x3[3]=b3.w;
                        lv[0]=lB.x; lv[1]=lB.y; lv[2]=lB.z; lv[3]=lB.w;
                    }
                    #pragma unroll
                    for (int j = 0; j < 4; j++) {
                        float e0 = __expf(x0[j]), e1 = __expf(x1[j]);
                        float e2 = __expf(x2[j]), e3 = __expf(x3[j]);
                        float inv = __frcp_rn((e0 + e1) + (e2 + e3));
                        float s[NCn] = {e0 * inv, e1 * inv, e2 * inv, e3 * inv};
                        const int lab = lv[j];
                        #pragma unroll
                        for (int c = 0; c < NCn; c++) {
                            float f = (lab == c) ? 1.0f : 0.0f;
                            inter[c] = fmaf(f, s[c], inter[c]);
                            uni[c]  += s[c] + f;
                        }
                    }
                }
            }

            __shared__ float sred[8][256];
            #pragma unroll
            for (int q = 0; q < NCn; q++) {
                sred[q][t]     = inter[q];
                sred[4 + q][t] = uni[q];
            }
            __syncthreads();
            const int w = t >> 5, lane = t & 31;
            float v = sred[w][lane];
            #pragma unroll
            for (int j = 1; j < 8; j++) v += sred[w][lane + 32 * j];
            #pragma unroll
            for (int o = 16; o > 0; o >>= 1)
                v += __shfl_down_sync(0xffffffffu, v, o);
            if (lane == 0) g_part[b][seg][w] = (double)v;
        } else {
            // ---------------- patch means: idx = sub-8 ----------------------
            const int idx  = sub - NSEG;
            const int s    = idx >> 3;      // 0 = oconf, 1 = aconf
            const int band = idx & 7;
            const float4* src = (const float4*)((s ? aconf : oconf)
                                  + (size_t)b * NPIX + band * Hn * IMGn);
            float acc = 0.0f;
            #pragma unroll
            for (int it = 0; it < 8; it++) {
                float4 v = src[it * 256 + t];
                acc += (v.x + v.y) + (v.z + v.w);
            }
            __shared__ float sacc[256];
            sacc[t] = acc;
            __syncthreads();
            if (t < 8) {
                float tot = 0.0f;
                #pragma unroll
                for (int g = 0; g < 4; g++)
                    #pragma unroll
                    for (int j = 0; j < 8; j++)
                        tot += sacc[g * 64 + t * 8 + j];
                float mean = tot * (1.0f / (Hn * Hn));
                if (s) g_amean[b][band * 8 + t] = mean;
                else   g_omean[b][band * 8 + t] = mean;
            }
        }

        // ---- arrival: 24th producer block for sample b computes its map ----
        __syncthreads();
        __threadfence();
        __shared__ int s_win;
        if (t == 0)
            s_win = (atomicAdd(&g_done[b], 1u) == ARRIVALS - 1) ? 1 : 0;
        __syncthreads();
        if (s_win) { __threadfence(); do_map(b, t); }

    } else {
        // ================= scatter: wait for map, then copy 16 rows =========
        const int m    = blk - NB_S1;
        const int b    = m >> 4;
        const int band = m & 15;            // 16 dest rows: band*16..band*16+15

        if (t == 0) {
            while (atomicAdd(&g_ready[b], 0u) == 0u) __nanosleep(64);
        }
        __syncthreads();
        __threadfence();   // acquire: map visible

        const int r  = t >> 6;              // 0..3
        const int c4 = t & 63;
        const int x  = c4 << 2;
        const int y0 = (band << 4) + r;     // rows y0, +4, +8, +12 (same patch)
        const int p  = ((y0 >> 5) << 3) | (x >> 5);

        const int v    = *(volatile int*)&g_map[b][p];   // bypass L1
        const int q    = v & 255;
        const bool sel = (v & 256) != 0;
        const int sx   = ((q & 7) << 5) | (x & 31);
        const int qy   = (q >> 3) << 5;

        const size_t bpl4 = (size_t)b * NP4;
        const float4* img4 = (const float4*)(sel ? aimg : oimg);
        const int4*   lab4 = (const int4*)  (sel ? alab : olab);
        const float4* cnf4 = (const float4*)(sel ? aconf : oconf);
        float4* o4 = (float4*)out;

        const size_t ib4 = (size_t)b * Cn * NP4;
        const size_t LB4 = (size_t)Bn * Cn * NP4;
        const size_t CB4 = LB4 + (size_t)Bn * NP4;

        #pragma unroll
        for (int half = 0; half < 2; half++) {
            const int yA = y0 + half * 8;            // rows yA and yA+4
            const size_t d0 = (size_t)yA * 64 + c4;
            const size_t d1 = d0 + 4 * 64;
            const size_t s0 = ((size_t)(qy | (yA & 31)) * IMGn + sx) >> 2;
            const size_t s1 = s0 + 4 * 64;

            // batch: 10 loads in flight, then 10 streaming stores.
            // labels/conf: LAST use of the L2-retained lines -> .cs
            float4 i0a = __ldcs(&img4[ib4 + 0 * NP4 + s0]);
            float4 i1a = __ldcs(&img4[ib4 + 1 * NP4 + s0]);
            float4 i2a = __ldcs(&img4[ib4 + 2 * NP4 + s0]);
            float4 i0b = __ldcs(&img4[ib4 + 0 * NP4 + s1]);
            float4 i1b = __ldcs(&img4[ib4 + 1 * NP4 + s1]);
            float4 i2b = __ldcs(&img4[ib4 + 2 * NP4 + s1]);
            int4   lva = __ldcs(&lab4[bpl4 + s0]);
            int4   lvb = __ldcs(&lab4[bpl4 + s1]);
            float4 cva = __ldcs(&cnf4[bpl4 + s0]);
            float4 cvb = __ldcs(&cnf4[bpl4 + s1]);

            __stcs(&o4[ib4 + 0 * NP4 + d0], i0a);
            __stcs(&o4[ib4 + 1 * NP4 + d0], i1a);
            __stcs(&o4[ib4 + 2 * NP4 + d0], i2a);
            __stcs(&o4[ib4 + 0 * NP4 + d1], i0b);
            __stcs(&o4[ib4 + 1 * NP4 + d1], i1b);
            __stcs(&o4[ib4 + 2 * NP4 + d1], i2b);
            __stcs(&o4[LB4 + bpl4 + d0],
                   make_float4((float)lva.x, (float)lva.y,
                               (float)lva.z, (float)lva.w));
            __stcs(&o4[LB4 + bpl4 + d1],
                   make_float4((float)lvb.x, (float)lvb.y,
                               (float)lvb.z, (float)lvb.w));
            __stcs(&o4[CB4 + bpl4 + d0], cva);
            __stcs(&o4[CB4 + bpl4 + d1], cvb);
        }

        // reset protocol: last scatter block for b clears flags for replay
        __syncthreads();
        if (t == 0) {
            if (atomicAdd(&g_sdone[b], 1u) == 15u) {
                g_sdone[b] = 0;
                atomicExch(&g_ready[b], 0u);
            }
        }
    }
}

extern "C" void kernel_launch(void* const* d_in, const int* in_sizes, int n_in,
                              void* d_out, int out_size) {
    const float* oimage = (const float*)d_in[0];
    const float* aimage = (const float*)d_in[1];
    const int*   olabel = (const int*)  d_in[2];
    const int*   alabel = (const int*)  d_in[3];
    const float* oconf  = (const float*)d_in[4];
    const float* aconf  = (const float*)d_in[5];
    const float* pred   = (const float*)d_in[6];
    float* out = (float*)d_out;

    k_fused<<<NB_S1 + NB_SC, 256>>>(pred, olabel, oimage, aimage,
                                    olabel, alabel, oconf, aconf, out);
}